// round 15
// baseline (speedup 1.0000x reference)
#include <cuda_runtime.h>
#include <cuda_fp16.h>
#include <cstdint>
#include <cstddef>

// Problem constants
#define BB   8
#define CC   62
#define GG   26
#define G3   17576
#define G2   676
#define NPT  32768
#define HH   1024
#define YSZ  (BB*3*NPT)

#define NB1 1099
#define NB2 69
#define NB3 5

typedef unsigned long long u64;

// ---------------- scratch ----------------
__device__ float g_csum[BB * G3];
__device__ float g_bsum[BB * NB1];
__device__ int   g_counts[BB * G3];
__device__ int   g_offs[BB * G3];
__device__ int   g_sorted[BB * NPT];
__device__ __align__(16) __half g_w1h[HH * 64];
__device__ float4 g_pack[HH];   // (b1, w2_0, w2_1, w2_2)

// ---------------- PTX helpers ----------------
__device__ __forceinline__ uint32_t smem_u32(const void* p) {
    uint32_t a;
    asm("{ .reg .u64 t; cvta.to.shared.u64 t, %1; cvt.u32.u64 %0, t; }" : "=r"(a) : "l"(p));
    return a;
}
__device__ __forceinline__ void cp_async16(uint32_t smem_dst, const void* gmem_src) {
    asm volatile("cp.async.ca.shared.global [%0], [%1], 16;" :: "r"(smem_dst), "l"(gmem_src));
}
__device__ __forceinline__ void cp_commit() { asm volatile("cp.async.commit_group;"); }
template <int N>
__device__ __forceinline__ void cp_wait() { asm volatile("cp.async.wait_group %0;" :: "n"(N)); }

__device__ __forceinline__ void ldsm_x4(uint32_t* r, uint32_t addr) {
    asm volatile("ldmatrix.sync.aligned.m8n8.x4.shared.b16 {%0,%1,%2,%3}, [%4];"
                 : "=r"(r[0]), "=r"(r[1]), "=r"(r[2]), "=r"(r[3]) : "r"(addr));
}
__device__ __forceinline__ void mma16816h(float* d, const uint32_t* a, const uint32_t* b) {
    asm volatile(
        "mma.sync.aligned.m16n8k16.row.col.f32.f16.f16.f32 "
        "{%0,%1,%2,%3}, {%4,%5,%6,%7}, {%8,%9}, {%0,%1,%2,%3};"
        : "+f"(d[0]), "+f"(d[1]), "+f"(d[2]), "+f"(d[3])
        : "r"(a[0]), "r"(a[1]), "r"(a[2]), "r"(a[3]), "r"(b[0]), "r"(b[1]));
}
__device__ __forceinline__ u64 pack2(float lo, float hi) {
    u64 r;
    asm("mov.b64 %0, {%1, %2};" : "=l"(r) : "f"(lo), "f"(hi));
    return r;
}
__device__ __forceinline__ void unpack2(float& lo, float& hi, u64 v) {
    asm("mov.b64 {%0, %1}, %2;" : "=f"(lo), "=f"(hi) : "l"(v));
}
__device__ __forceinline__ u64 fma2(u64 a, u64 b, u64 c) {
    u64 d;
    asm("fma.rn.f32x2 %0, %1, %2, %3;" : "=l"(d) : "l"(a), "l"(b), "l"(c));
    return d;
}

// ---------------- kernel: prep W1 (fp16) + pack ----------------
__global__ void k_prepw(const float* __restrict__ W1, const float* __restrict__ b1,
                        const float* __restrict__ W2) {
    int i = blockIdx.x * blockDim.x + threadIdx.x;
    if (i < HH * 64) g_w1h[i] = __float2half(W1[i]);
    if (i < HH) g_pack[i] = make_float4(b1[i], W2[i], W2[HH + i], W2[2 * HH + i]);
}

// ---------------- kernel 1: XLA:CPU ReduceWindowRewriter-exact cumsum ----------------
#define CS_SMEM (G3 * 4)
__global__ __launch_bounds__(1024) void k_cumsum_rw(const float* __restrict__ dens) {
    extern __shared__ float sd[];
    __shared__ float T1[NB1];
    __shared__ float T2[NB2];
    __shared__ float T3[NB3];
    const int b = blockIdx.x;
    const int tid = threadIdx.x;

    {
        const float4* src = reinterpret_cast<const float4*>(dens + (size_t)b * G3);
        float4* dst = reinterpret_cast<float4*>(sd);
        int4* cz = reinterpret_cast<int4*>(g_counts + b * G3);
        for (int i = tid; i < G3 / 4; i += 1024) {
            dst[i] = src[i];
            cz[i] = make_int4(0, 0, 0, 0);
        }
    }
    __syncthreads();
    for (int j = tid; j < NB1; j += 1024) {
        const int s0 = j * 16, e0 = min(s0 + 16, G3);
        float s = 0.f;
        for (int i = s0; i < e0; ++i) s += sd[i];
        T1[j] = s;
    }
    __syncthreads();
    if (tid < NB2) {
        const int s1 = tid * 16, e1 = min(s1 + 16, NB1);
        float s = 0.f;
        for (int i = s1; i < e1; ++i) s += T1[i];
        T2[tid] = s;
    }
    __syncthreads();
    if (tid == 0) {
        for (int j = 0; j < NB3; ++j) {
            const int s2 = j * 16, e2 = min(s2 + 16, NB2);
            float s = 0.f;
            for (int i = s2; i < e2; ++i) s += T2[i];
            T3[j] = s;
        }
        float s = 0.f;
        for (int j = 0; j < NB3; ++j) { s += T3[j]; T3[j] = s; }
        for (int j2 = 0; j2 < NB3; ++j2) {
            const float P = (j2 > 0) ? T3[j2 - 1] : 0.0f;
            float sr = 0.f;
            const int s2 = j2 * 16, e2 = min(j2 * 16 + 16, NB2);
            for (int i = s2; i < e2; ++i) { sr += T2[i]; T2[i] = sr + P; }
        }
    }
    __syncthreads();
    if (tid < NB2) {
        const float P = (tid > 0) ? T2[tid - 1] : 0.0f;
        float sr = 0.f;
        const int s1 = tid * 16, e1 = min(tid * 16 + 16, NB1);
        for (int i = s1; i < e1; ++i) { sr += T1[i]; T1[i] = sr + P; }
    }
    __syncthreads();
    float* cs = g_csum + (size_t)b * G3;
    for (int j = tid; j < NB1; j += 1024) {
        const float P = (j > 0) ? T1[j - 1] : 0.0f;
        float sr = 0.f;
        const int s0 = j * 16, e0 = min(j * 16 + 16, G3);
        float last = 0.f;
        for (int i = s0; i < e0; ++i) {
            sr += sd[i];
            last = sr + P;
            cs[i] = last;
        }
        g_bsum[b * NB1 + j] = last;
    }
}

// ---------------- kernel 2: sample (smem coarse search) -> histogram ----------------
__global__ __launch_bounds__(256) void k_sample(const float* __restrict__ u) {
    __shared__ float sbs[NB1];
    const int b = blockIdx.x >> 4;
    const int sl = blockIdx.x & 15;
    for (int i = threadIdx.x; i < NB1; i += 256) sbs[i] = g_bsum[b * NB1 + i];
    __syncthreads();
    const float total = sbs[NB1 - 1];
    const float* cs = g_csum + (size_t)b * G3;
    const int base = sl * 2048;
    #pragma unroll
    for (int r = 0; r < 8; ++r) {
        const int n = base + r * 256 + threadIdx.x;
        float t = u[b * NPT + n] * total;
        int lo = 0, hi = NB1;
        while (lo < hi) {
            int mid = (lo + hi) >> 1;
            if (sbs[mid] <= t) lo = mid + 1; else hi = mid;
        }
        int idx;
        if (lo >= NB1) {
            idx = G3 - 1;
        } else {
            int s = lo * 16;
            int e = min(s + 16, G3);
            while (s < e) {
                int mid = (s + e) >> 1;
                if (cs[mid] <= t) s = mid + 1; else e = mid;
            }
            idx = min(s, G3 - 1);
        }
        atomicAdd(&g_counts[b * G3 + idx], 1);
    }
}

// ---------------- kernel 3a: offsets scan (8 CTAs) ----------------
#define BINS_PT 18
__global__ __launch_bounds__(1024) void k_scan() {
    const int b = blockIdx.x;
    const int* cnt = g_counts + b * G3;
    int* offs = g_offs + b * G3;
    __shared__ int wsum[32];
    const int tid = threadIdx.x;
    const int lane = tid & 31, wid = tid >> 5;
    const int base = tid * BINS_PT;

    int c[BINS_PT], pre[BINS_PT];
    int s = 0;
    #pragma unroll
    for (int r = 0; r < BINS_PT; ++r) {
        const int i = base + r;
        c[r] = (i < G3) ? cnt[i] : 0;
        pre[r] = s; s += c[r];
    }
    int x = s;
    #pragma unroll
    for (int d = 1; d < 32; d <<= 1) {
        int y = __shfl_up_sync(0xffffffffu, x, d);
        if (lane >= d) x += y;
    }
    if (lane == 31) wsum[wid] = x;
    __syncthreads();
    if (wid == 0) {
        int t = wsum[lane];
        #pragma unroll
        for (int d = 1; d < 32; d <<= 1) {
            int y = __shfl_up_sync(0xffffffffu, t, d);
            if (lane >= d) t += y;
        }
        wsum[lane] = t;
    }
    __syncthreads();
    const int excl = (x - s) + (wid ? wsum[wid - 1] : 0);
    #pragma unroll
    for (int r = 0; r < BINS_PT; ++r) {
        const int i = base + r;
        if (i < G3) offs[i] = excl + pre[r];
    }
}

// ---------------- kernel 3b: run-length emit (64 CTAs) ----------------
#define SLICE 2197
__global__ __launch_bounds__(256) void k_emit() {
    const int b = blockIdx.x >> 3;
    const int sl = blockIdx.x & 7;
    const int* cnt = g_counts + b * G3;
    const int* offs = g_offs + b * G3;
    int* srt = g_sorted + b * NPT;
    const int lo = sl * SLICE;
    const int hiB = min(lo + SLICE, G3);
    for (int i = lo + threadIdx.x; i < hiB; i += 256) {
        const int o = offs[i];
        const int c = cnt[i];
        for (int k = 0; k < c; ++k) srt[o + k] = i;
    }
}

// ---------------- kernel 4: fp16 HMMA fused MLP, 1 tile/warp, 3 CTAs/SM ----------------
// Single product A_hi(fp16) x W_hi(fp16). 256 thr / 8 warps / 128 points per CTA.
// W streamed in 16 x 64-h chunks through 4-stage cp.async ring, ONE sync/chunk.
// Epilogue: packed f32x2 FMA, bit-identical order to R13.
#define VPITCHB 144                    // 72 halves (64 used + pad)
#define SM_VHI  0                      // 128*144 = 18432
#define SM_W    18432                  // 4 bufs x 9216
#define WBUFSZ  9216                   // 64*144
#define SM_PACK 55296                  // 1024 float4 = 16384
#define SM_IDX  71680                  // 128 ints
#define SM_TOTAL (SM_IDX + 512 + 64)

__global__ __launch_bounds__(256, 3) void k_mlp_mma(
    const float* __restrict__ x, const float* __restrict__ rnd,
    const float* __restrict__ b2, float* __restrict__ out)
{
    extern __shared__ char smem[];
    const uint32_t sbase = smem_u32(smem);
    const int tid = threadIdx.x;
    const int wid = tid >> 5;
    const int lane = tid & 31;
    const int b = blockIdx.y;
    const int j0 = blockIdx.x * 128;

    int* sIdx = (int*)(smem + SM_IDX);
    const float4* sPack = (const float4*)(smem + SM_PACK);
    float4* sPackW = (float4*)(smem + SM_PACK);

    // one 64-h chunk = 512 cp16; 256 thr -> 2 each
    #define KICKW(CH, BUFI) {                                                   \
        _Pragma("unroll")                                                       \
        for (int i = 0; i < 2; ++i) {                                           \
            int lin = i * 256 + tid;                                            \
            int r = lin >> 3;                                                   \
            int sg = lin & 7;                                                   \
            const __half* src = g_w1h + ((CH) * 64 + r) * 64 + sg * 8;          \
            cp_async16(sbase + SM_W + (BUFI) * WBUFSZ + r * VPITCHB + sg * 16,  \
                       src);                                                    \
        }                                                                       \
        cp_commit(); }

    KICKW(0, 0);
    KICKW(1, 1);
    KICKW(2, 2);

    if (tid < 128) sIdx[tid] = g_sorted[b * NPT + j0 + tid];
    #pragma unroll
    for (int k = 0; k < 4; ++k) sPackW[tid + k * 256] = g_pack[tid + k * 256];
    __syncthreads();

    // gather V -> fp16 smem (2 threads per point)
    {
        const int p = tid & 127;
        const int c0 = tid >> 7;
        const int gidx = sIdx[p];
        const float* xb = x + (size_t)b * CC * G3 + gidx;
        __half* vhi = (__half*)(smem + SM_VHI);
        for (int c = c0; c < CC; c += 2)
            vhi[p * 72 + c] = __float2half(xb[(size_t)c * G3]);
        vhi[p * 72 + 62 + c0] =
            __float2half(rnd[((size_t)b * 2 + c0) * NPT + j0 + p] * 2.0f - 1.0f);
    }
    __syncthreads();

    // A fragment: 1 tile x 16 regs, loaded once
    uint32_t ahi[16];
    {
        const uint32_t rowoff = (uint32_t)((wid * 16 + (lane & 15)) * VPITCHB
                                           + ((lane >> 4) << 4));
        #pragma unroll
        for (int ks = 0; ks < 4; ++ks)
            ldsm_x4(&ahi[ks * 4], sbase + SM_VHI + rowoff + ks * 32);
    }

    // packed accumulators: (row r, row r+8) pairs for y/z/w
    u64 accY = 0ull, accZ = 0ull, accW = 0ull;

    const uint32_t bladdr = (uint32_t)(((lane & 7) * VPITCHB) + ((lane >> 3) << 4));

    for (int ch = 0; ch < 16; ++ch) {
        if (ch <= 13)      cp_wait<2>();
        else if (ch == 14) cp_wait<1>();
        else               cp_wait<0>();
        __syncthreads();
        if (ch < 13) KICKW(ch + 3, (ch + 3) & 3);

        const uint32_t wbuf = sbase + SM_W + (ch & 3) * WBUFSZ;

        #pragma unroll
        for (int t8 = 0; t8 < 8; ++t8) {
            uint32_t bh[8];
            const uint32_t ba = wbuf + t8 * 8 * VPITCHB + bladdr;
            ldsm_x4(&bh[0], ba);
            ldsm_x4(&bh[4], ba + 64);

            const int h0 = ch * 64 + t8 * 8 + ((lane & 3) << 1);
            const float4 pk0 = sPack[h0];
            const float4 pk1 = sPack[h0 + 1];

            float d0[4] = {pk0.x, pk1.x, pk0.x, pk1.x};
            #pragma unroll
            for (int ks = 0; ks < 4; ++ks)
                mma16816h(d0, &ahi[ks * 4], &bh[ks * 2]);

            const u64 S0 = pack2(fmaxf(d0[0], 0.f), fmaxf(d0[2], 0.f));
            const u64 S1 = pack2(fmaxf(d0[1], 0.f), fmaxf(d0[3], 0.f));
            accY = fma2(pack2(pk0.y, pk0.y), S0, fma2(pack2(pk1.y, pk1.y), S1, accY));
            accZ = fma2(pack2(pk0.z, pk0.z), S0, fma2(pack2(pk1.z, pk1.z), S1, accZ));
            accW = fma2(pack2(pk0.w, pk0.w), S0, fma2(pack2(pk1.w, pk1.w), S1, accW));
        }
    }

    // unpack to 6 floats, quad reduce
    float acc[6];
    unpack2(acc[0], acc[3], accY);
    unpack2(acc[1], acc[4], accZ);
    unpack2(acc[2], acc[5], accW);
    #pragma unroll
    for (int q = 0; q < 6; ++q) {
        acc[q] += __shfl_xor_sync(0xffffffffu, acc[q], 1);
        acc[q] += __shfl_xor_sync(0xffffffffu, acc[q], 2);
    }

    if ((lane & 3) == 0) {
        const float bb0 = __ldg(&b2[0]);
        const float bb1 = __ldg(&b2[1]);
        const float bb2 = __ldg(&b2[2]);
        #pragma unroll
        for (int half = 0; half < 2; ++half) {
            const int p = wid * 16 + (lane >> 2) + half * 8;
            float v0 = acc[half * 3 + 0] + bb0;
            float v1 = acc[half * 3 + 1] + bb1;
            float v2 = acc[half * 3 + 2] + bb2;
            const float nrm = sqrtf(v0 * v0 + v1 * v1 + v2 * v2);
            const float rg = fmaxf(nrm - 0.06661733875264912f, 0.0f);
            const int gidx = sIdx[p];
            const int ix = gidx / G2;
            const int rem = gidx - ix * G2;
            const int iy = rem / GG;
            const int iz = rem - iy * GG;
            const float ox = ((float)ix + 0.5f) * 2.0f / 26.0f - 1.0f;
            const float oy = ((float)iy + 0.5f) * 2.0f / 26.0f - 1.0f;
            const float oz = ((float)iz + 0.5f) * 2.0f / 26.0f - 1.0f;
            const size_t j = (size_t)j0 + p;
            out[((size_t)b * 3 + 0) * NPT + j] = v0 + ox;
            out[((size_t)b * 3 + 1) * NPT + j] = v1 + oy;
            out[((size_t)b * 3 + 2) * NPT + j] = v2 + oz;
            out[(size_t)YSZ + (size_t)b * NPT + j] = rg;
        }
    }
}

// ---------------- launch ----------------
extern "C" void kernel_launch(void* const* d_in, const int* in_sizes, int n_in,
                              void* d_out, int out_size) {
    const float* x    = (const float*)d_in[0];
    const float* dens = (const float*)d_in[1];
    const float* rnd  = (const float*)d_in[2];
    const float* u    = (const float*)d_in[3];
    const float* W1   = (const float*)d_in[4];
    const float* b1   = (const float*)d_in[5];
    const float* W2   = (const float*)d_in[6];
    const float* b2   = (const float*)d_in[7];
    float* out = (float*)d_out;

    cudaFuncSetAttribute(k_cumsum_rw, cudaFuncAttributeMaxDynamicSharedMemorySize, CS_SMEM);
    cudaFuncSetAttribute(k_mlp_mma, cudaFuncAttributeMaxDynamicSharedMemorySize, SM_TOTAL);

    k_prepw<<<(HH * 64 + 255) / 256, 256>>>(W1, b1, W2);
    k_cumsum_rw<<<BB, 1024, CS_SMEM>>>(dens);
    k_sample<<<BB * 16, 256>>>(u);
    k_scan<<<BB, 1024>>>();
    k_emit<<<BB * 8, 256>>>();
    dim3 grid(NPT / 128, BB);
    k_mlp_mma<<<grid, 256, SM_TOTAL>>>(x, rnd, b2, out);
}

// round 16
// speedup vs baseline: 1.1975x; 1.1975x over previous
#include <cuda_runtime.h>
#include <cuda_fp16.h>
#include <cstdint>
#include <cstddef>

// Problem constants
#define BB   8
#define CC   62
#define GG   26
#define G3   17576
#define G2   676
#define NPT  32768
#define HH   1024
#define YSZ  (BB*3*NPT)

#define NB1 1099
#define NB2 69
#define NB3 5

typedef unsigned long long u64;

// ---------------- scratch ----------------
__device__ float g_csum[BB * G3];
__device__ float g_bsum[BB * NB1];
__device__ int   g_counts[BB * G3];
__device__ int   g_offs[BB * G3];
__device__ int   g_sorted[BB * NPT];
__device__ __align__(16) __half g_w1h[HH * 64];
__device__ float4 g_pack[HH];   // (b1, w2_0, w2_1, w2_2)

// ---------------- PTX helpers ----------------
__device__ __forceinline__ uint32_t smem_u32(const void* p) {
    uint32_t a;
    asm("{ .reg .u64 t; cvta.to.shared.u64 t, %1; cvt.u32.u64 %0, t; }" : "=r"(a) : "l"(p));
    return a;
}
__device__ __forceinline__ void cp_async16(uint32_t smem_dst, const void* gmem_src) {
    asm volatile("cp.async.ca.shared.global [%0], [%1], 16;" :: "r"(smem_dst), "l"(gmem_src));
}
__device__ __forceinline__ void cp_commit() { asm volatile("cp.async.commit_group;"); }
template <int N>
__device__ __forceinline__ void cp_wait() { asm volatile("cp.async.wait_group %0;" :: "n"(N)); }

__device__ __forceinline__ void ldsm_x4(uint32_t* r, uint32_t addr) {
    asm volatile("ldmatrix.sync.aligned.m8n8.x4.shared.b16 {%0,%1,%2,%3}, [%4];"
                 : "=r"(r[0]), "=r"(r[1]), "=r"(r[2]), "=r"(r[3]) : "r"(addr));
}
__device__ __forceinline__ void mma16816h(float* d, const uint32_t* a, const uint32_t* b) {
    asm volatile(
        "mma.sync.aligned.m16n8k16.row.col.f32.f16.f16.f32 "
        "{%0,%1,%2,%3}, {%4,%5,%6,%7}, {%8,%9}, {%0,%1,%2,%3};"
        : "+f"(d[0]), "+f"(d[1]), "+f"(d[2]), "+f"(d[3])
        : "r"(a[0]), "r"(a[1]), "r"(a[2]), "r"(a[3]), "r"(b[0]), "r"(b[1]));
}
__device__ __forceinline__ u64 pack2(float lo, float hi) {
    u64 r;
    asm("mov.b64 %0, {%1, %2};" : "=l"(r) : "f"(lo), "f"(hi));
    return r;
}
__device__ __forceinline__ void unpack2(float& lo, float& hi, u64 v) {
    asm("mov.b64 {%0, %1}, %2;" : "=f"(lo), "=f"(hi) : "l"(v));
}
__device__ __forceinline__ u64 fma2(u64 a, u64 b, u64 c) {
    u64 d;
    asm("fma.rn.f32x2 %0, %1, %2, %3;" : "=l"(d) : "l"(a), "l"(b), "l"(c));
    return d;
}

// ---------------- kernel 1: cumsum (XLA ReduceWindowRewriter-exact) + W prep fused ----------------
#define CS_SMEM (G3 * 4)
__global__ __launch_bounds__(1024) void k_cumsum_rw(
    const float* __restrict__ dens, const float* __restrict__ W1,
    const float* __restrict__ b1, const float* __restrict__ W2)
{
    extern __shared__ float sd[];
    __shared__ float T1[NB1];
    __shared__ float T2[NB2];
    __shared__ float T3[NB3];
    const int b = blockIdx.x;
    const int tid = threadIdx.x;

    // fused W prep (independent, spread across the 8 CTAs)
    {
        const int gtid = b * 1024 + tid;
        #pragma unroll
        for (int r = 0; r < 8; ++r) {
            const int i = gtid + r * 8192;
            g_w1h[i] = __float2half(W1[i]);
        }
        if (b == 0) g_pack[tid] = make_float4(b1[tid], W2[tid], W2[HH + tid], W2[2 * HH + tid]);
    }

    {
        const float4* src = reinterpret_cast<const float4*>(dens + (size_t)b * G3);
        float4* dst = reinterpret_cast<float4*>(sd);
        int4* cz = reinterpret_cast<int4*>(g_counts + b * G3);
        for (int i = tid; i < G3 / 4; i += 1024) {
            dst[i] = src[i];
            cz[i] = make_int4(0, 0, 0, 0);
        }
    }
    __syncthreads();
    for (int j = tid; j < NB1; j += 1024) {
        const int s0 = j * 16, e0 = min(s0 + 16, G3);
        float s = 0.f;
        for (int i = s0; i < e0; ++i) s += sd[i];
        T1[j] = s;
    }
    __syncthreads();
    if (tid < NB2) {
        const int s1 = tid * 16, e1 = min(s1 + 16, NB1);
        float s = 0.f;
        for (int i = s1; i < e1; ++i) s += T1[i];
        T2[tid] = s;
    }
    __syncthreads();
    if (tid == 0) {
        for (int j = 0; j < NB3; ++j) {
            const int s2 = j * 16, e2 = min(s2 + 16, NB2);
            float s = 0.f;
            for (int i = s2; i < e2; ++i) s += T2[i];
            T3[j] = s;
        }
        float s = 0.f;
        for (int j = 0; j < NB3; ++j) { s += T3[j]; T3[j] = s; }
        for (int j2 = 0; j2 < NB3; ++j2) {
            const float P = (j2 > 0) ? T3[j2 - 1] : 0.0f;
            float sr = 0.f;
            const int s2 = j2 * 16, e2 = min(j2 * 16 + 16, NB2);
            for (int i = s2; i < e2; ++i) { sr += T2[i]; T2[i] = sr + P; }
        }
    }
    __syncthreads();
    if (tid < NB2) {
        const float P = (tid > 0) ? T2[tid - 1] : 0.0f;
        float sr = 0.f;
        const int s1 = tid * 16, e1 = min(tid * 16 + 16, NB1);
        for (int i = s1; i < e1; ++i) { sr += T1[i]; T1[i] = sr + P; }
    }
    __syncthreads();
    float* cs = g_csum + (size_t)b * G3;
    for (int j = tid; j < NB1; j += 1024) {
        const float P = (j > 0) ? T1[j - 1] : 0.0f;
        float sr = 0.f;
        const int s0 = j * 16, e0 = min(j * 16 + 16, G3);
        float last = 0.f;
        for (int i = s0; i < e0; ++i) {
            sr += sd[i];
            last = sr + P;
            cs[i] = last;
        }
        g_bsum[b * NB1 + j] = last;
    }
}

// ---------------- kernel 2: sample (smem coarse search) -> histogram ----------------
__global__ __launch_bounds__(256) void k_sample(const float* __restrict__ u) {
    __shared__ float sbs[NB1];
    const int b = blockIdx.x >> 4;
    const int sl = blockIdx.x & 15;
    for (int i = threadIdx.x; i < NB1; i += 256) sbs[i] = g_bsum[b * NB1 + i];
    __syncthreads();
    const float total = sbs[NB1 - 1];
    const float* cs = g_csum + (size_t)b * G3;
    const int base = sl * 2048;
    #pragma unroll
    for (int r = 0; r < 8; ++r) {
        const int n = base + r * 256 + threadIdx.x;
        float t = u[b * NPT + n] * total;
        int lo = 0, hi = NB1;
        while (lo < hi) {
            int mid = (lo + hi) >> 1;
            if (sbs[mid] <= t) lo = mid + 1; else hi = mid;
        }
        int idx;
        if (lo >= NB1) {
            idx = G3 - 1;
        } else {
            int s = lo * 16;
            int e = min(s + 16, G3);
            while (s < e) {
                int mid = (s + e) >> 1;
                if (cs[mid] <= t) s = mid + 1; else e = mid;
            }
            idx = min(s, G3 - 1);
        }
        atomicAdd(&g_counts[b * G3 + idx], 1);
    }
}

// ---------------- kernel 3a: offsets scan (8 CTAs) ----------------
#define BINS_PT 18
__global__ __launch_bounds__(1024) void k_scan() {
    const int b = blockIdx.x;
    const int* cnt = g_counts + b * G3;
    int* offs = g_offs + b * G3;
    __shared__ int wsum[32];
    const int tid = threadIdx.x;
    const int lane = tid & 31, wid = tid >> 5;
    const int base = tid * BINS_PT;

    int c[BINS_PT], pre[BINS_PT];
    int s = 0;
    #pragma unroll
    for (int r = 0; r < BINS_PT; ++r) {
        const int i = base + r;
        c[r] = (i < G3) ? cnt[i] : 0;
        pre[r] = s; s += c[r];
    }
    int x = s;
    #pragma unroll
    for (int d = 1; d < 32; d <<= 1) {
        int y = __shfl_up_sync(0xffffffffu, x, d);
        if (lane >= d) x += y;
    }
    if (lane == 31) wsum[wid] = x;
    __syncthreads();
    if (wid == 0) {
        int t = wsum[lane];
        #pragma unroll
        for (int d = 1; d < 32; d <<= 1) {
            int y = __shfl_up_sync(0xffffffffu, t, d);
            if (lane >= d) t += y;
        }
        wsum[lane] = t;
    }
    __syncthreads();
    const int excl = (x - s) + (wid ? wsum[wid - 1] : 0);
    #pragma unroll
    for (int r = 0; r < BINS_PT; ++r) {
        const int i = base + r;
        if (i < G3) offs[i] = excl + pre[r];
    }
}

// ---------------- kernel 3b: run-length emit (64 CTAs) ----------------
#define SLICE 2197
__global__ __launch_bounds__(256) void k_emit() {
    const int b = blockIdx.x >> 3;
    const int sl = blockIdx.x & 7;
    const int* cnt = g_counts + b * G3;
    const int* offs = g_offs + b * G3;
    int* srt = g_sorted + b * NPT;
    const int lo = sl * SLICE;
    const int hiB = min(lo + SLICE, G3);
    for (int i = lo + threadIdx.x; i < hiB; i += 256) {
        const int o = offs[i];
        const int c = cnt[i];
        for (int k = 0; k < c; ++k) srt[o + k] = i;
    }
}

// ---------------- kernel 4: fp16 HMMA fused MLP (R13 tiling, 128-h chunks, 3-buf ring) ----------------
// Single product A_hi(fp16) x W_hi(fp16). 256 thr / 8 warps / 256 pts, 2 CTAs/SM.
// W streamed in 8 x 128-h chunks through a 3-stage cp.async ring, ONE sync/chunk (8 total).
// h-traversal order identical to R13 -> bit-identical accumulation.
#define VPITCHB 144                    // 72 halves (64 used + pad)
#define SM_VHI  0                      // 256*144 = 36864
#define SM_W    36864                  // 3 bufs x 18432 = 55296
#define WBUFSZ  18432                  // 128*144
#define SM_PACK 92160                  // 1024 float4 = 16384
#define SM_IDX  108544                 // 256 ints
#define SM_TOTAL (SM_IDX + 1024 + 64)

__global__ __launch_bounds__(256, 2) void k_mlp_mma(
    const float* __restrict__ x, const float* __restrict__ rnd,
    const float* __restrict__ b2, float* __restrict__ out)
{
    extern __shared__ char smem[];
    const uint32_t sbase = smem_u32(smem);
    const int tid = threadIdx.x;
    const int wid = tid >> 5;
    const int lane = tid & 31;
    const int b = blockIdx.y;
    const int j0 = blockIdx.x * 256;

    int* sIdx = (int*)(smem + SM_IDX);
    const float4* sPack = (const float4*)(smem + SM_PACK);
    float4* sPackW = (float4*)(smem + SM_PACK);

    // one 128-h chunk = 1024 cp16; 256 thr -> 4 each
    #define KICKW(CH, BUFI) {                                                   \
        _Pragma("unroll")                                                       \
        for (int i = 0; i < 4; ++i) {                                           \
            int lin = i * 256 + tid;                                            \
            int r = lin >> 3;                                                   \
            int sg = lin & 7;                                                   \
            const __half* src = g_w1h + ((CH) * 128 + r) * 64 + sg * 8;         \
            cp_async16(sbase + SM_W + (BUFI) * WBUFSZ + r * VPITCHB + sg * 16,  \
                       src);                                                    \
        }                                                                       \
        cp_commit(); }

    KICKW(0, 0);
    KICKW(1, 1);

    sIdx[tid] = g_sorted[b * NPT + j0 + tid];
    #pragma unroll
    for (int k = 0; k < 4; ++k) sPackW[tid + k * 256] = g_pack[tid + k * 256];
    __syncthreads();

    // gather V -> fp16 smem (1 thread per point)
    {
        const int p = tid;
        const int gidx = sIdx[p];
        const float* xb = x + (size_t)b * CC * G3 + gidx;
        __half* vhi = (__half*)(smem + SM_VHI);
        #pragma unroll 2
        for (int c = 0; c < CC; ++c)
            vhi[p * 72 + c] = __float2half(xb[(size_t)c * G3]);
        #pragma unroll
        for (int c0 = 0; c0 < 2; ++c0)
            vhi[p * 72 + 62 + c0] =
                __float2half(rnd[((size_t)b * 2 + c0) * NPT + j0 + p] * 2.0f - 1.0f);
    }
    __syncthreads();   // V visible to all warps

    // A fragments: 2 tiles x 16 regs, loaded once
    uint32_t ahi[2][16];
    #pragma unroll
    for (int tile = 0; tile < 2; ++tile) {
        const uint32_t rowoff = (uint32_t)((wid * 32 + tile * 16 + (lane & 15)) * VPITCHB
                                           + ((lane >> 4) << 4));
        #pragma unroll
        for (int ks = 0; ks < 4; ++ks)
            ldsm_x4(&ahi[tile][ks * 4], sbase + SM_VHI + rowoff + ks * 32);
    }

    // packed accumulators: per tile, (row r, row r+8) pairs for y/z/w
    u64 accY[2], accZ[2], accW[2];
    #pragma unroll
    for (int t = 0; t < 2; ++t) { accY[t] = 0ull; accZ[t] = 0ull; accW[t] = 0ull; }

    const uint32_t bladdr = (uint32_t)(((lane & 7) * VPITCHB) + ((lane >> 3) << 4));

    for (int ch = 0; ch < 8; ++ch) {
        if (ch <= 6) cp_wait<1>();
        else         cp_wait<0>();
        __syncthreads();   // cross-thread cp.async visibility + ring buf free
        if (ch < 6) KICKW(ch + 2, (ch + 2) % 3);

        const uint32_t wbuf = sbase + SM_W + (ch % 3) * WBUFSZ;

        #pragma unroll 8
        for (int t8 = 0; t8 < 16; ++t8) {
            uint32_t bh[8];
            const uint32_t ba = wbuf + t8 * 8 * VPITCHB + bladdr;
            ldsm_x4(&bh[0], ba);
            ldsm_x4(&bh[4], ba + 64);

            const int h0 = ch * 128 + t8 * 8 + ((lane & 3) << 1);
            const float4 pk0 = sPack[h0];
            const float4 pk1 = sPack[h0 + 1];
            const u64 Y0 = pack2(pk0.y, pk0.y), Y1 = pack2(pk1.y, pk1.y);
            const u64 Z0 = pack2(pk0.z, pk0.z), Z1 = pack2(pk1.z, pk1.z);
            const u64 W0 = pack2(pk0.w, pk0.w), W1p = pack2(pk1.w, pk1.w);

            // two independent 4-deep mma chains, bias in init
            float d0[4] = {pk0.x, pk1.x, pk0.x, pk1.x};
            float d1[4] = {pk0.x, pk1.x, pk0.x, pk1.x};
            #pragma unroll
            for (int ks = 0; ks < 4; ++ks) {
                mma16816h(d0, &ahi[0][ks * 4], &bh[ks * 2]);
                mma16816h(d1, &ahi[1][ks * 4], &bh[ks * 2]);
            }

            {
                const u64 S0 = pack2(fmaxf(d0[0], 0.f), fmaxf(d0[2], 0.f));
                const u64 S1 = pack2(fmaxf(d0[1], 0.f), fmaxf(d0[3], 0.f));
                accY[0] = fma2(Y0, S0, fma2(Y1, S1, accY[0]));
                accZ[0] = fma2(Z0, S0, fma2(Z1, S1, accZ[0]));
                accW[0] = fma2(W0, S0, fma2(W1p, S1, accW[0]));
            }
            {
                const u64 S0 = pack2(fmaxf(d1[0], 0.f), fmaxf(d1[2], 0.f));
                const u64 S1 = pack2(fmaxf(d1[1], 0.f), fmaxf(d1[3], 0.f));
                accY[1] = fma2(Y0, S0, fma2(Y1, S1, accY[1]));
                accZ[1] = fma2(Z0, S0, fma2(Z1, S1, accZ[1]));
                accW[1] = fma2(W0, S0, fma2(W1p, S1, accW[1]));
            }
        }
    }

    // unpack to 6 floats per tile, quad reduce
    float acc[2][6];
    #pragma unroll
    for (int t = 0; t < 2; ++t) {
        unpack2(acc[t][0], acc[t][3], accY[t]);
        unpack2(acc[t][1], acc[t][4], accZ[t]);
        unpack2(acc[t][2], acc[t][5], accW[t]);
    }
    #pragma unroll
    for (int t = 0; t < 2; ++t)
        #pragma unroll
        for (int q = 0; q < 6; ++q) {
            acc[t][q] += __shfl_xor_sync(0xffffffffu, acc[t][q], 1);
            acc[t][q] += __shfl_xor_sync(0xffffffffu, acc[t][q], 2);
        }

    if ((lane & 3) == 0) {
        const float bb0 = __ldg(&b2[0]);
        const float bb1 = __ldg(&b2[1]);
        const float bb2 = __ldg(&b2[2]);
        #pragma unroll
        for (int tile = 0; tile < 2; ++tile) {
            #pragma unroll
            for (int half = 0; half < 2; ++half) {
                const int p = wid * 32 + tile * 16 + (lane >> 2) + half * 8;
                float v0 = acc[tile][half * 3 + 0] + bb0;
                float v1 = acc[tile][half * 3 + 1] + bb1;
                float v2 = acc[tile][half * 3 + 2] + bb2;
                const float nrm = sqrtf(v0 * v0 + v1 * v1 + v2 * v2);
                const float rg = fmaxf(nrm - 0.06661733875264912f, 0.0f);
                const int gidx = sIdx[p];
                const int ix = gidx / G2;
                const int rem = gidx - ix * G2;
                const int iy = rem / GG;
                const int iz = rem - iy * GG;
                const float ox = ((float)ix + 0.5f) * 2.0f / 26.0f - 1.0f;
                const float oy = ((float)iy + 0.5f) * 2.0f / 26.0f - 1.0f;
                const float oz = ((float)iz + 0.5f) * 2.0f / 26.0f - 1.0f;
                const size_t j = (size_t)j0 + p;
                out[((size_t)b * 3 + 0) * NPT + j] = v0 + ox;
                out[((size_t)b * 3 + 1) * NPT + j] = v1 + oy;
                out[((size_t)b * 3 + 2) * NPT + j] = v2 + oz;
                out[(size_t)YSZ + (size_t)b * NPT + j] = rg;
            }
        }
    }
}

// ---------------- launch ----------------
extern "C" void kernel_launch(void* const* d_in, const int* in_sizes, int n_in,
                              void* d_out, int out_size) {
    const float* x    = (const float*)d_in[0];
    const float* dens = (const float*)d_in[1];
    const float* rnd  = (const float*)d_in[2];
    const float* u    = (const float*)d_in[3];
    const float* W1   = (const float*)d_in[4];
    const float* b1   = (const float*)d_in[5];
    const float* W2   = (const float*)d_in[6];
    const float* b2   = (const float*)d_in[7];
    float* out = (float*)d_out;

    cudaFuncSetAttribute(k_cumsum_rw, cudaFuncAttributeMaxDynamicSharedMemorySize, CS_SMEM);
    cudaFuncSetAttribute(k_mlp_mma, cudaFuncAttributeMaxDynamicSharedMemorySize, SM_TOTAL);

    k_cumsum_rw<<<BB, 1024, CS_SMEM>>>(dens, W1, b1, W2);
    k_sample<<<BB * 16, 256>>>(u);
    k_scan<<<BB, 1024>>>();
    k_emit<<<BB * 8, 256>>>();
    dim3 grid(NPT / 256, BB);
    k_mlp_mma<<<grid, 256, SM_TOTAL>>>(x, rnd, b2, out);
}

// round 17
// speedup vs baseline: 1.2662x; 1.0573x over previous
#include <cuda_runtime.h>
#include <cuda_fp16.h>
#include <cstdint>
#include <cstddef>

// Problem constants
#define BB   8
#define CC   62
#define GG   26
#define G3   17576
#define G2   676
#define NPT  32768
#define HH   1024
#define YSZ  (BB*3*NPT)

#define NB1 1099
#define NB2 69
#define NB3 5

typedef unsigned long long u64;

// ---------------- scratch ----------------
__device__ float g_csum[BB * G3];
__device__ float g_bsum[BB * NB1];
__device__ int   g_counts[BB * G3];
__device__ int   g_offs[BB * G3];
__device__ int   g_sorted[BB * NPT];
__device__ __align__(16) __half g_w1h[HH * 64];
__device__ float4 g_pack[HH];   // (b1, w2_0, w2_1, w2_2)

// ---------------- PTX helpers ----------------
__device__ __forceinline__ uint32_t smem_u32(const void* p) {
    uint32_t a;
    asm("{ .reg .u64 t; cvta.to.shared.u64 t, %1; cvt.u32.u64 %0, t; }" : "=r"(a) : "l"(p));
    return a;
}
__device__ __forceinline__ void cp_async16(uint32_t smem_dst, const void* gmem_src) {
    asm volatile("cp.async.ca.shared.global [%0], [%1], 16;" :: "r"(smem_dst), "l"(gmem_src));
}
__device__ __forceinline__ void cp_commit() { asm volatile("cp.async.commit_group;"); }
template <int N>
__device__ __forceinline__ void cp_wait() { asm volatile("cp.async.wait_group %0;" :: "n"(N)); }

__device__ __forceinline__ void ldsm_x4(uint32_t* r, uint32_t addr) {
    asm volatile("ldmatrix.sync.aligned.m8n8.x4.shared.b16 {%0,%1,%2,%3}, [%4];"
                 : "=r"(r[0]), "=r"(r[1]), "=r"(r[2]), "=r"(r[3]) : "r"(addr));
}
__device__ __forceinline__ void mma16816h(float* d, const uint32_t* a, const uint32_t* b) {
    asm volatile(
        "mma.sync.aligned.m16n8k16.row.col.f32.f16.f16.f32 "
        "{%0,%1,%2,%3}, {%4,%5,%6,%7}, {%8,%9}, {%0,%1,%2,%3};"
        : "+f"(d[0]), "+f"(d[1]), "+f"(d[2]), "+f"(d[3])
        : "r"(a[0]), "r"(a[1]), "r"(a[2]), "r"(a[3]), "r"(b[0]), "r"(b[1]));
}
__device__ __forceinline__ u64 pack2(float lo, float hi) {
    u64 r;
    asm("mov.b64 %0, {%1, %2};" : "=l"(r) : "f"(lo), "f"(hi));
    return r;
}
__device__ __forceinline__ void unpack2(float& lo, float& hi, u64 v) {
    asm("mov.b64 {%0, %1}, %2;" : "=f"(lo), "=f"(hi) : "l"(v));
}
__device__ __forceinline__ u64 fma2(u64 a, u64 b, u64 c) {
    u64 d;
    asm("fma.rn.f32x2 %0, %1, %2, %3;" : "=l"(d) : "l"(a), "l"(b), "l"(c));
    return d;
}

// ---------------- kernel 1: cumsum (XLA ReduceWindowRewriter-exact) + W prep fused ----------------
#define CS_SMEM (G3 * 4)
__global__ __launch_bounds__(1024) void k_cumsum_rw(
    const float* __restrict__ dens, const float* __restrict__ W1,
    const float* __restrict__ b1, const float* __restrict__ W2)
{
    extern __shared__ float sd[];
    __shared__ float T1[NB1];
    __shared__ float T2[NB2];
    __shared__ float T3[NB3];
    const int b = blockIdx.x;
    const int tid = threadIdx.x;

    // fused W prep (independent, spread across the 8 CTAs)
    {
        const int gtid = b * 1024 + tid;
        #pragma unroll
        for (int r = 0; r < 8; ++r) {
            const int i = gtid + r * 8192;
            g_w1h[i] = __float2half(W1[i]);
        }
        if (b == 0) g_pack[tid] = make_float4(b1[tid], W2[tid], W2[HH + tid], W2[2 * HH + tid]);
    }

    {
        const float4* src = reinterpret_cast<const float4*>(dens + (size_t)b * G3);
        float4* dst = reinterpret_cast<float4*>(sd);
        int4* cz = reinterpret_cast<int4*>(g_counts + b * G3);
        for (int i = tid; i < G3 / 4; i += 1024) {
            dst[i] = src[i];
            cz[i] = make_int4(0, 0, 0, 0);
        }
    }
    __syncthreads();
    for (int j = tid; j < NB1; j += 1024) {
        const int s0 = j * 16, e0 = min(s0 + 16, G3);
        float s = 0.f;
        for (int i = s0; i < e0; ++i) s += sd[i];
        T1[j] = s;
    }
    __syncthreads();
    if (tid < NB2) {
        const int s1 = tid * 16, e1 = min(s1 + 16, NB1);
        float s = 0.f;
        for (int i = s1; i < e1; ++i) s += T1[i];
        T2[tid] = s;
    }
    __syncthreads();
    if (tid == 0) {
        for (int j = 0; j < NB3; ++j) {
            const int s2 = j * 16, e2 = min(s2 + 16, NB2);
            float s = 0.f;
            for (int i = s2; i < e2; ++i) s += T2[i];
            T3[j] = s;
        }
        float s = 0.f;
        for (int j = 0; j < NB3; ++j) { s += T3[j]; T3[j] = s; }
        for (int j2 = 0; j2 < NB3; ++j2) {
            const float P = (j2 > 0) ? T3[j2 - 1] : 0.0f;
            float sr = 0.f;
            const int s2 = j2 * 16, e2 = min(j2 * 16 + 16, NB2);
            for (int i = s2; i < e2; ++i) { sr += T2[i]; T2[i] = sr + P; }
        }
    }
    __syncthreads();
    if (tid < NB2) {
        const float P = (tid > 0) ? T2[tid - 1] : 0.0f;
        float sr = 0.f;
        const int s1 = tid * 16, e1 = min(tid * 16 + 16, NB1);
        for (int i = s1; i < e1; ++i) { sr += T1[i]; T1[i] = sr + P; }
    }
    __syncthreads();
    float* cs = g_csum + (size_t)b * G3;
    for (int j = tid; j < NB1; j += 1024) {
        const float P = (j > 0) ? T1[j - 1] : 0.0f;
        float sr = 0.f;
        const int s0 = j * 16, e0 = min(j * 16 + 16, G3);
        float last = 0.f;
        for (int i = s0; i < e0; ++i) {
            sr += sd[i];
            last = sr + P;
            cs[i] = last;
        }
        g_bsum[b * NB1 + j] = last;
    }
}

// ---------------- kernel 2: sample (smem coarse search) -> histogram ----------------
// 256 CTAs: 32 per batch, 256 thr, 1024 samples each (4/thread).
__global__ __launch_bounds__(256) void k_sample(const float* __restrict__ u) {
    __shared__ float sbs[NB1];
    const int b = blockIdx.x >> 5;
    const int sl = blockIdx.x & 31;
    for (int i = threadIdx.x; i < NB1; i += 256) sbs[i] = g_bsum[b * NB1 + i];
    __syncthreads();
    const float total = sbs[NB1 - 1];
    const float* cs = g_csum + (size_t)b * G3;
    const int base = sl * 1024;
    #pragma unroll
    for (int r = 0; r < 4; ++r) {
        const int n = base + r * 256 + threadIdx.x;
        float t = u[b * NPT + n] * total;
        int lo = 0, hi = NB1;
        while (lo < hi) {
            int mid = (lo + hi) >> 1;
            if (sbs[mid] <= t) lo = mid + 1; else hi = mid;
        }
        int idx;
        if (lo >= NB1) {
            idx = G3 - 1;
        } else {
            int s = lo * 16;
            int e = min(s + 16, G3);
            while (s < e) {
                int mid = (s + e) >> 1;
                if (cs[mid] <= t) s = mid + 1; else e = mid;
            }
            idx = min(s, G3 - 1);
        }
        atomicAdd(&g_counts[b * G3 + idx], 1);
    }
}

// ---------------- kernel 3a: offsets scan (8 CTAs) ----------------
#define BINS_PT 18
__global__ __launch_bounds__(1024) void k_scan() {
    const int b = blockIdx.x;
    const int* cnt = g_counts + b * G3;
    int* offs = g_offs + b * G3;
    __shared__ int wsum[32];
    const int tid = threadIdx.x;
    const int lane = tid & 31, wid = tid >> 5;
    const int base = tid * BINS_PT;

    int c[BINS_PT], pre[BINS_PT];
    int s = 0;
    #pragma unroll
    for (int r = 0; r < BINS_PT; ++r) {
        const int i = base + r;
        c[r] = (i < G3) ? cnt[i] : 0;
        pre[r] = s; s += c[r];
    }
    int x = s;
    #pragma unroll
    for (int d = 1; d < 32; d <<= 1) {
        int y = __shfl_up_sync(0xffffffffu, x, d);
        if (lane >= d) x += y;
    }
    if (lane == 31) wsum[wid] = x;
    __syncthreads();
    if (wid == 0) {
        int t = wsum[lane];
        #pragma unroll
        for (int d = 1; d < 32; d <<= 1) {
            int y = __shfl_up_sync(0xffffffffu, t, d);
            if (lane >= d) t += y;
        }
        wsum[lane] = t;
    }
    __syncthreads();
    const int excl = (x - s) + (wid ? wsum[wid - 1] : 0);
    #pragma unroll
    for (int r = 0; r < BINS_PT; ++r) {
        const int i = base + r;
        if (i < G3) offs[i] = excl + pre[r];
    }
}

// ---------------- kernel 3b: run-length emit (256 CTAs) ----------------
#define ESLICE 550   // ceil(G3 / 32)
__global__ __launch_bounds__(256) void k_emit() {
    const int b = blockIdx.x >> 5;
    const int sl = blockIdx.x & 31;
    const int* cnt = g_counts + b * G3;
    const int* offs = g_offs + b * G3;
    int* srt = g_sorted + b * NPT;
    const int lo = sl * ESLICE;
    const int hiB = min(lo + ESLICE, G3);
    for (int i = lo + threadIdx.x; i < hiB; i += 256) {
        const int o = offs[i];
        const int c = cnt[i];
        for (int k = 0; k < c; ++k) srt[o + k] = i;
    }
}

// ---------------- kernel 4: fp16 HMMA fused MLP (unchanged R16 champion) ----------------
#define VPITCHB 144                    // 72 halves (64 used + pad)
#define SM_VHI  0                      // 256*144 = 36864
#define SM_W    36864                  // 3 bufs x 18432 = 55296
#define WBUFSZ  18432                  // 128*144
#define SM_PACK 92160                  // 1024 float4 = 16384
#define SM_IDX  108544                 // 256 ints
#define SM_TOTAL (SM_IDX + 1024 + 64)

__global__ __launch_bounds__(256, 2) void k_mlp_mma(
    const float* __restrict__ x, const float* __restrict__ rnd,
    const float* __restrict__ b2, float* __restrict__ out)
{
    extern __shared__ char smem[];
    const uint32_t sbase = smem_u32(smem);
    const int tid = threadIdx.x;
    const int wid = tid >> 5;
    const int lane = tid & 31;
    const int b = blockIdx.y;
    const int j0 = blockIdx.x * 256;

    int* sIdx = (int*)(smem + SM_IDX);
    const float4* sPack = (const float4*)(smem + SM_PACK);
    float4* sPackW = (float4*)(smem + SM_PACK);

    #define KICKW(CH, BUFI) {                                                   \
        _Pragma("unroll")                                                       \
        for (int i = 0; i < 4; ++i) {                                           \
            int lin = i * 256 + tid;                                            \
            int r = lin >> 3;                                                   \
            int sg = lin & 7;                                                   \
            const __half* src = g_w1h + ((CH) * 128 + r) * 64 + sg * 8;         \
            cp_async16(sbase + SM_W + (BUFI) * WBUFSZ + r * VPITCHB + sg * 16,  \
                       src);                                                    \
        }                                                                       \
        cp_commit(); }

    KICKW(0, 0);
    KICKW(1, 1);

    sIdx[tid] = g_sorted[b * NPT + j0 + tid];
    #pragma unroll
    for (int k = 0; k < 4; ++k) sPackW[tid + k * 256] = g_pack[tid + k * 256];
    __syncthreads();

    // gather V -> fp16 smem (1 thread per point)
    {
        const int p = tid;
        const int gidx = sIdx[p];
        const float* xb = x + (size_t)b * CC * G3 + gidx;
        __half* vhi = (__half*)(smem + SM_VHI);
        #pragma unroll 2
        for (int c = 0; c < CC; ++c)
            vhi[p * 72 + c] = __float2half(xb[(size_t)c * G3]);
        #pragma unroll
        for (int c0 = 0; c0 < 2; ++c0)
            vhi[p * 72 + 62 + c0] =
                __float2half(rnd[((size_t)b * 2 + c0) * NPT + j0 + p] * 2.0f - 1.0f);
    }
    __syncthreads();   // V visible to all warps

    // A fragments: 2 tiles x 16 regs, loaded once
    uint32_t ahi[2][16];
    #pragma unroll
    for (int tile = 0; tile < 2; ++tile) {
        const uint32_t rowoff = (uint32_t)((wid * 32 + tile * 16 + (lane & 15)) * VPITCHB
                                           + ((lane >> 4) << 4));
        #pragma unroll
        for (int ks = 0; ks < 4; ++ks)
            ldsm_x4(&ahi[tile][ks * 4], sbase + SM_VHI + rowoff + ks * 32);
    }

    // packed accumulators: per tile, (row r, row r+8) pairs for y/z/w
    u64 accY[2], accZ[2], accW[2];
    #pragma unroll
    for (int t = 0; t < 2; ++t) { accY[t] = 0ull; accZ[t] = 0ull; accW[t] = 0ull; }

    const uint32_t bladdr = (uint32_t)(((lane & 7) * VPITCHB) + ((lane >> 3) << 4));

    for (int ch = 0; ch < 8; ++ch) {
        if (ch <= 6) cp_wait<1>();
        else         cp_wait<0>();
        __syncthreads();
        if (ch < 6) KICKW(ch + 2, (ch + 2) % 3);

        const uint32_t wbuf = sbase + SM_W + (ch % 3) * WBUFSZ;

        #pragma unroll 8
        for (int t8 = 0; t8 < 16; ++t8) {
            uint32_t bh[8];
            const uint32_t ba = wbuf + t8 * 8 * VPITCHB + bladdr;
            ldsm_x4(&bh[0], ba);
            ldsm_x4(&bh[4], ba + 64);

            const int h0 = ch * 128 + t8 * 8 + ((lane & 3) << 1);
            const float4 pk0 = sPack[h0];
            const float4 pk1 = sPack[h0 + 1];
            const u64 Y0 = pack2(pk0.y, pk0.y), Y1 = pack2(pk1.y, pk1.y);
            const u64 Z0 = pack2(pk0.z, pk0.z), Z1 = pack2(pk1.z, pk1.z);
            const u64 W0 = pack2(pk0.w, pk0.w), W1p = pack2(pk1.w, pk1.w);

            float d0[4] = {pk0.x, pk1.x, pk0.x, pk1.x};
            float d1[4] = {pk0.x, pk1.x, pk0.x, pk1.x};
            #pragma unroll
            for (int ks = 0; ks < 4; ++ks) {
                mma16816h(d0, &ahi[0][ks * 4], &bh[ks * 2]);
                mma16816h(d1, &ahi[1][ks * 4], &bh[ks * 2]);
            }

            {
                const u64 S0 = pack2(fmaxf(d0[0], 0.f), fmaxf(d0[2], 0.f));
                const u64 S1 = pack2(fmaxf(d0[1], 0.f), fmaxf(d0[3], 0.f));
                accY[0] = fma2(Y0, S0, fma2(Y1, S1, accY[0]));
                accZ[0] = fma2(Z0, S0, fma2(Z1, S1, accZ[0]));
                accW[0] = fma2(W0, S0, fma2(W1p, S1, accW[0]));
            }
            {
                const u64 S0 = pack2(fmaxf(d1[0], 0.f), fmaxf(d1[2], 0.f));
                const u64 S1 = pack2(fmaxf(d1[1], 0.f), fmaxf(d1[3], 0.f));
                accY[1] = fma2(Y0, S0, fma2(Y1, S1, accY[1]));
                accZ[1] = fma2(Z0, S0, fma2(Z1, S1, accZ[1]));
                accW[1] = fma2(W0, S0, fma2(W1p, S1, accW[1]));
            }
        }
    }

    // unpack to 6 floats per tile, quad reduce
    float acc[2][6];
    #pragma unroll
    for (int t = 0; t < 2; ++t) {
        unpack2(acc[t][0], acc[t][3], accY[t]);
        unpack2(acc[t][1], acc[t][4], accZ[t]);
        unpack2(acc[t][2], acc[t][5], accW[t]);
    }
    #pragma unroll
    for (int t = 0; t < 2; ++t)
        #pragma unroll
        for (int q = 0; q < 6; ++q) {
            acc[t][q] += __shfl_xor_sync(0xffffffffu, acc[t][q], 1);
            acc[t][q] += __shfl_xor_sync(0xffffffffu, acc[t][q], 2);
        }

    if ((lane & 3) == 0) {
        const float bb0 = __ldg(&b2[0]);
        const float bb1 = __ldg(&b2[1]);
        const float bb2 = __ldg(&b2[2]);
        #pragma unroll
        for (int tile = 0; tile < 2; ++tile) {
            #pragma unroll
            for (int half = 0; half < 2; ++half) {
                const int p = wid * 32 + tile * 16 + (lane >> 2) + half * 8;
                float v0 = acc[tile][half * 3 + 0] + bb0;
                float v1 = acc[tile][half * 3 + 1] + bb1;
                float v2 = acc[tile][half * 3 + 2] + bb2;
                const float nrm = sqrtf(v0 * v0 + v1 * v1 + v2 * v2);
                const float rg = fmaxf(nrm - 0.06661733875264912f, 0.0f);
                const int gidx = sIdx[p];
                const int ix = gidx / G2;
                const int rem = gidx - ix * G2;
                const int iy = rem / GG;
                const int iz = rem - iy * GG;
                const float ox = ((float)ix + 0.5f) * 2.0f / 26.0f - 1.0f;
                const float oy = ((float)iy + 0.5f) * 2.0f / 26.0f - 1.0f;
                const float oz = ((float)iz + 0.5f) * 2.0f / 26.0f - 1.0f;
                const size_t j = (size_t)j0 + p;
                out[((size_t)b * 3 + 0) * NPT + j] = v0 + ox;
                out[((size_t)b * 3 + 1) * NPT + j] = v1 + oy;
                out[((size_t)b * 3 + 2) * NPT + j] = v2 + oz;
                out[(size_t)YSZ + (size_t)b * NPT + j] = rg;
            }
        }
    }
}

// ---------------- launch ----------------
extern "C" void kernel_launch(void* const* d_in, const int* in_sizes, int n_in,
                              void* d_out, int out_size) {
    const float* x    = (const float*)d_in[0];
    const float* dens = (const float*)d_in[1];
    const float* rnd  = (const float*)d_in[2];
    const float* u    = (const float*)d_in[3];
    const float* W1   = (const float*)d_in[4];
    const float* b1   = (const float*)d_in[5];
    const float* W2   = (const float*)d_in[6];
    const float* b2   = (const float*)d_in[7];
    float* out = (float*)d_out;

    cudaFuncSetAttribute(k_cumsum_rw, cudaFuncAttributeMaxDynamicSharedMemorySize, CS_SMEM);
    cudaFuncSetAttribute(k_mlp_mma, cudaFuncAttributeMaxDynamicSharedMemorySize, SM_TOTAL);

    k_cumsum_rw<<<BB, 1024, CS_SMEM>>>(dens, W1, b1, W2);
    k_sample<<<BB * 32, 256>>>(u);
    k_scan<<<BB, 1024>>>();
    k_emit<<<BB * 32, 256>>>();
    dim3 grid(NPT / 256, BB);
    k_mlp_mma<<<grid, 256, SM_TOTAL>>>(x, rnd, b2, out);
}